// round 10
// baseline (speedup 1.0000x reference)
#include <cuda_runtime.h>
#include <cstdint>

// Problem constants
#define BQ 16
#define DQ 128
#define TQ 4096
#define VQ 1024

#define TILE_M 128
#define TILE_N 128
#define NCHUNK 8
#define QCAP 6144
#define NTHREADS 512

// Dynamic SMEM layout (bytes)
#define OFF_RES     0          // 128 x u64 packed (score,idx)
#define OFF_ROWMIN  1024       // 128 x u32
#define OFF_QN      1536       // u32 queue counter
#define OFF_MARG    1600       // 128 floats: per-row margin (SX during load)
#define OFF_TILEMAX 2112       // u32 (abs-max of x tile, float bits)
#define OFF_CSQ     2176       // 1024 floats
#define OFF_QUEUE   6272       // QCAP x u32 (24KB)
#define OFF_AF      30848      // fp32 A [128][132]
#define AF_STRIDE   132
#define OFF_B       98432      // int8 B tiles, 3 x 16KB (triple buffer)
#define BTILE       16384
#define SMEM_TOTAL  147584

__device__ float g_csq[VQ];
__device__ float g_cabrow[VQ];   // per-row sum|c|
__device__ float g_cmaxrow[VQ];  // per-row max|c|
__device__ float g_sc;           // codebook scale = max|c|/127
__device__ float g_cab;          // max_v sum|c|
__device__ signed char g_ci8[VQ * DQ];

// ---------------------------------------------------------------------------
__device__ __forceinline__ uint32_t smem_u32(const void* p) {
    uint32_t a;
    asm("{ .reg .u64 t; cvta.to.shared.u64 t, %1; cvt.u32.u64 %0, t; }"
        : "=r"(a) : "l"(p));
    return a;
}

#define LDMX4(r, addr) \
    asm volatile("ldmatrix.sync.aligned.m8n8.x4.shared.b16 {%0,%1,%2,%3}, [%4];" \
        : "=r"((r)[0]), "=r"((r)[1]), "=r"((r)[2]), "=r"((r)[3]) \
        : "r"(addr))

__device__ __forceinline__ void mma_s8(int* c, const uint32_t* a,
                                       const uint32_t* b) {
    asm volatile(
        "mma.sync.aligned.m16n8k32.row.col.s32.s8.s8.s32 "
        "{%0,%1,%2,%3}, {%4,%5,%6,%7}, {%8,%9}, {%0,%1,%2,%3};"
        : "+r"(c[0]), "+r"(c[1]), "+r"(c[2]), "+r"(c[3])
        : "r"(a[0]), "r"(a[1]), "r"(a[2]), "r"(a[3]), "r"(b[0]), "r"(b[1]));
}

#define CP_ASYNC16(dst, src) \
    asm volatile("cp.async.cg.shared.global [%0], [%1], 16;" \
        :: "r"(dst), "l"(src))
#define CP_COMMIT() asm volatile("cp.async.commit_group;" ::: "memory")
#define CP_WAIT2() asm volatile("cp.async.wait_group 2;" ::: "memory")

// Swizzled byte offset inside a (rows x 128) INT8 tile: 128B rows, 16B
// chunks, chunk column XOR'd with row%8 -> conflict-free ldmatrix.
__device__ __forceinline__ uint32_t tswz8(int row, int chunk) {
    return (uint32_t)(row * 128 + ((chunk ^ (row & 7)) << 4));
}

// Order-preserving float <-> uint
__device__ __forceinline__ unsigned fford(float f) {
    unsigned u = __float_as_uint(f);
    return (u & 0x80000000u) ? ~u : (u | 0x80000000u);
}
__device__ __forceinline__ float fford_inv(unsigned u) {
    unsigned b = (u & 0x80000000u) ? (u & 0x7fffffffu) : ~u;
    return __uint_as_float(b);
}

// Quantize 4 floats -> packed int8x4 (round-to-nearest, clamp +-127)
__device__ __forceinline__ uint32_t q4(float4 f, float inv) {
    int q0 = max(-127, min(127, __float2int_rn(f.x * inv)));
    int q1 = max(-127, min(127, __float2int_rn(f.y * inv)));
    int q2 = max(-127, min(127, __float2int_rn(f.z * inv)));
    int q3 = max(-127, min(127, __float2int_rn(f.w * inv)));
    return (uint32_t)(q0 & 0xff) | ((uint32_t)(q1 & 0xff) << 8) |
           ((uint32_t)(q2 & 0xff) << 16) | ((uint32_t)q3 << 24);
}

// ---------------------------------------------------------------------------
// Prep 1: per code row v (one warp): csq, sum|c|, max|c|
// ---------------------------------------------------------------------------
__global__ void prep1_kernel(const float* __restrict__ cb) {
    int v = (blockIdx.x * blockDim.x + threadIdx.x) >> 5;
    int lane = threadIdx.x & 31;
    if (v >= VQ) return;
    const float4 x4 = *(const float4*)(cb + (size_t)v * DQ + lane * 4);
    float s = x4.x * x4.x + x4.y * x4.y + x4.z * x4.z + x4.w * x4.w;
    float ab = fabsf(x4.x) + fabsf(x4.y) + fabsf(x4.z) + fabsf(x4.w);
    float mx = fmaxf(fmaxf(fabsf(x4.x), fabsf(x4.y)),
                     fmaxf(fabsf(x4.z), fabsf(x4.w)));
#pragma unroll
    for (int off = 16; off; off >>= 1) {
        s += __shfl_down_sync(0xffffffffu, s, off);
        ab += __shfl_down_sync(0xffffffffu, ab, off);
        mx = fmaxf(mx, __shfl_down_sync(0xffffffffu, mx, off));
    }
    if (lane == 0) {
        g_csq[v] = s;
        g_cabrow[v] = ab;
        g_cmaxrow[v] = mx;
    }
}

// ---------------------------------------------------------------------------
// Prep 2: single block: reduce cmax/cab, quantize codebook to int8
// ---------------------------------------------------------------------------
__global__ void prep2_kernel(const float* __restrict__ cb) {
    __shared__ float smax[1024], sab[1024];
    int tid = threadIdx.x;
    smax[tid] = g_cmaxrow[tid];
    sab[tid] = g_cabrow[tid];
    __syncthreads();
#pragma unroll
    for (int off = 512; off; off >>= 1) {
        if (tid < off) {
            smax[tid] = fmaxf(smax[tid], smax[tid + off]);
            sab[tid] = fmaxf(sab[tid], sab[tid + off]);
        }
        __syncthreads();
    }
    float cmax = fmaxf(smax[0], 1e-20f);
    if (tid == 0) {
        g_sc = cmax / 127.0f;
        g_cab = sab[0];
    }
    float inv = 127.0f / cmax;
    for (int i = tid; i < VQ * DQ; i += 1024) {
        int q = max(-127, min(127, __float2int_rn(cb[i] * inv)));
        g_ci8[i] = (signed char)q;
    }
}

// ---------------------------------------------------------------------------
// Main: int8 IMMA screen (A frags persistent in regs) -> candidate queue ->
// exact fp32 rescore -> codes + fused quantized gather.
// 512 threads, 16 warps (4x4), warp tile 32x32, CTA 128x128x128, 8 chunks.
// ---------------------------------------------------------------------------
__global__ void __launch_bounds__(NTHREADS, 1)
vq_kernel(const float* __restrict__ latents, const float* __restrict__ cb,
          float* __restrict__ codes, float* __restrict__ quant) {
    extern __shared__ unsigned char sm[];
    const uint32_t smb = smem_u32(sm);
    const int tid = threadIdx.x;
    const int lane = tid & 31;
    const int wid = tid >> 5;
    const int warp_m = wid & 3;    // 4 m-tiles of 32 rows
    const int warp_n = wid >> 2;   // 4 n-tiles of 32 cols
    const int b = blockIdx.y;
    const int t0 = blockIdx.x * TILE_M;

    unsigned long long* res = (unsigned long long*)(sm + OFF_RES);
    unsigned* rowmin = (unsigned*)(sm + OFF_ROWMIN);
    unsigned* qn = (unsigned*)(sm + OFF_QN);
    float* marg = (float*)(sm + OFF_MARG);        // SX during load phase
    unsigned* tmax = (unsigned*)(sm + OFF_TILEMAX);
    float* csq_s = (float*)(sm + OFF_CSQ);
    unsigned* queue = (unsigned*)(sm + OFF_QUEUE);
    float* Af = (float*)(sm + OFF_AF);

    const float scv = g_sc;
    const float cabv = g_cab;

    // Prefetch int8 B chunks 0 and 1 (two committed groups)
#pragma unroll
    for (int pc = 0; pc < 2; pc++) {
        const signed char* src = g_ci8 + (size_t)pc * TILE_N * DQ;
        uint32_t dbase = smb + OFF_B + pc * BTILE;
        for (int i = tid; i < 1024; i += NTHREADS) {
            int n = i >> 3, c = i & 7;
            CP_ASYNC16(dbase + tswz8(n, c), (const void*)(src + n * DQ + c * 16));
        }
        CP_COMMIT();
    }

    if (tid < TILE_M) {
        res[tid] = ~0ull;
        rowmin[tid] = 0xFFFFFFFFu;
        marg[tid] = 0.f;   // SX accumulator
    }
    if (tid == 0) { *qn = 0; *tmax = 0; }
    for (int i = tid; i < VQ; i += NTHREADS) csq_s[i] = g_csq[i];
    __syncthreads();

    // A: latents[b][d][t0+t] -> fp32 smem + per-row sum|x| + tile max|x|
    {
        const float* xg = latents + (size_t)b * DQ * TQ + t0;
        float lmax = 0.f;
        for (int idx = tid; idx < DQ * TILE_M; idx += NTHREADS) {
            int d = idx >> 7;
            int t = idx & 127;     // coalesced over t
            float x = xg[(size_t)d * TQ + t];
            Af[t * AF_STRIDE + d] = x;
            float ax = fabsf(x);
            lmax = fmaxf(lmax, ax);
            atomicAdd(&marg[t], ax);
        }
        atomicMax(tmax, __float_as_uint(lmax));  // nonneg floats: uint order ok
    }
    __syncthreads();

    const float tilemax = fmaxf(__uint_as_float(*tmax), 1e-20f);
    const float sx = tilemax / 127.0f;
    const float twoS = 2.0f * sx * scv;
    const float inv_sx = 127.0f / tilemax;

    // Finalize per-row margin: margin = sc*SX + sx*CAB + 192*sx*sc (+slack)
    if (tid < TILE_M)
        marg[tid] = (scv * marg[tid] + sx * cabv + 192.f * sx * scv) * 1.01f
                    + 0.02f;

    // Load persistent A fragments (int8, quantized inline from Af).
    // m16n8k32 A frag: a0=(row g, k c4..c4+3), a1=(g+8, same), a2/a3 = +16 k.
    uint32_t afr[2][4][4];
    {
        const int g = lane >> 2;
        const int c4 = (lane & 3) << 2;
#pragma unroll
        for (int mi = 0; mi < 2; mi++) {
            int row = warp_m * 32 + mi * 16 + g;
            const float* r0 = Af + row * AF_STRIDE;
            const float* r8 = Af + (row + 8) * AF_STRIDE;
#pragma unroll
            for (int ks = 0; ks < 4; ks++) {
                int k = ks * 32 + c4;
                afr[mi][ks][0] = q4(*(const float4*)(r0 + k), inv_sx);
                afr[mi][ks][1] = q4(*(const float4*)(r8 + k), inv_sx);
                afr[mi][ks][2] = q4(*(const float4*)(r0 + k + 16), inv_sx);
                afr[mi][ks][3] = q4(*(const float4*)(r8 + k + 16), inv_sx);
            }
        }
    }
    __syncthreads();   // margins final before insert phase reads them

    // Per-thread B ldmatrix constants
    const int brow_in16 = (lane & 7) | ((lane >> 4) << 3);
    const int kcb = (lane >> 3) & 1;
    int bxr[2];
    uint32_t bbase[2];
#pragma unroll
    for (int n4 = 0; n4 < 2; n4++) {
        int row = warp_n * 32 + n4 * 16 + brow_in16;
        bxr[n4] = row & 7;
        bbase[n4] = (uint32_t)(row * 128);
    }

    for (int vc = 0; vc < NCHUNK; vc++) {
        const int v0 = vc * TILE_N;

        // Prefetch chunk vc+2 into buffer (vc+2)%3
        if (vc + 2 < NCHUNK) {
            const signed char* src = g_ci8 + (size_t)(v0 + 2 * TILE_N) * DQ;
            uint32_t dbase = smb + OFF_B + ((vc + 2) % 3) * BTILE;
            for (int i = tid; i < 1024; i += NTHREADS) {
                int n = i >> 3, c = i & 7;
                CP_ASYNC16(dbase + tswz8(n, c),
                           (const void*)(src + n * DQ + c * 16));
            }
        }
        CP_COMMIT();
        CP_WAIT2();
        __syncthreads();   // B[vc] visible; all warps past B[vc-3] reads

        int acc[2][4][4];
#pragma unroll
        for (int mi = 0; mi < 2; mi++)
#pragma unroll
            for (int ni = 0; ni < 4; ni++)
#pragma unroll
                for (int q = 0; q < 4; q++) acc[mi][ni][q] = 0;

        const uint32_t bsm = smb + OFF_B + (vc % 3) * BTILE;
#pragma unroll
        for (int ks = 0; ks < 4; ks++) {
            uint32_t bF[4][2];
#pragma unroll
            for (int n4 = 0; n4 < 2; n4++) {
                uint32_t chunk = (uint32_t)(((ks << 1) | kcb) ^ bxr[n4]);
                uint32_t r[4];
                LDMX4(r, bsm + bbase[n4] + (chunk << 4));
                bF[n4 * 2][0] = r[0]; bF[n4 * 2][1] = r[1];
                bF[n4 * 2 + 1][0] = r[2]; bF[n4 * 2 + 1][1] = r[3];
            }
#pragma unroll
            for (int mi = 0; mi < 2; mi++)
#pragma unroll
                for (int ni = 0; ni < 4; ni++)
                    mma_s8(acc[mi][ni], afr[mi][ks], bF[ni]);
        }

        // Scores: csq[v] - twoS*idot ; per-thread row mins -> rowmin atomics
        float sc_[2][4][4];
        float rm[4];
#pragma unroll
        for (int j = 0; j < 4; j++) rm[j] = 3.4e38f;
#pragma unroll
        for (int ni = 0; ni < 4; ni++) {
            int col0 = v0 + warp_n * 32 + ni * 8 + (lane & 3) * 2;
            float cs0 = csq_s[col0], cs1 = csq_s[col0 + 1];
#pragma unroll
            for (int mi = 0; mi < 2; mi++) {
                float* s = sc_[mi][ni];
                const int* c = acc[mi][ni];
                s[0] = fmaf(-twoS, (float)c[0], cs0);
                s[1] = fmaf(-twoS, (float)c[1], cs1);
                s[2] = fmaf(-twoS, (float)c[2], cs0);
                s[3] = fmaf(-twoS, (float)c[3], cs1);
                float m01 = fminf(s[0], s[1]), m23 = fminf(s[2], s[3]);
                if (m01 < rm[mi * 2]) rm[mi * 2] = m01;
                if (m23 < rm[mi * 2 + 1]) rm[mi * 2 + 1] = m23;
            }
        }
        // rowmin monotone-decreasing: no barrier needed (stale read = safe
        // looser threshold; writer of true min reads its own update).
#pragma unroll
        for (int j = 0; j < 4; j++) {
            int row = warp_m * 32 + (j >> 1) * 16 + (j & 1) * 8 + (lane >> 2);
            atomicMin(&rowmin[row], fford(rm[j]));
        }

        // Insert candidates within per-row margin of running row min
#pragma unroll
        for (int mi = 0; mi < 2; mi++) {
            int rA = warp_m * 32 + mi * 16 + (lane >> 2);
            float thA = fford_inv(rowmin[rA]) + marg[rA];
            float thB = fford_inv(rowmin[rA + 8]) + marg[rA + 8];
#pragma unroll
            for (int ni = 0; ni < 4; ni++) {
                int col0 = v0 + warp_n * 32 + ni * 8 + (lane & 3) * 2;
                const float* s = sc_[mi][ni];
                if (s[0] <= thA) {
                    unsigned k = atomicAdd(qn, 1u);
                    if (k < QCAP) queue[k] = ((unsigned)rA << 10) | col0;
                }
                if (s[1] <= thA) {
                    unsigned k = atomicAdd(qn, 1u);
                    if (k < QCAP) queue[k] = ((unsigned)rA << 10) | (col0 + 1);
                }
                if (s[2] <= thB) {
                    unsigned k = atomicAdd(qn, 1u);
                    if (k < QCAP) queue[k] = ((unsigned)(rA + 8) << 10) | col0;
                }
                if (s[3] <= thB) {
                    unsigned k = atomicAdd(qn, 1u);
                    if (k < QCAP) queue[k] = ((unsigned)(rA + 8) << 10) | (col0 + 1);
                }
            }
        }
    }
    __syncthreads();

    // Exact fp32 rescore of candidates: one warp per queue entry
    {
        unsigned n = *qn;
        if (n > QCAP) n = QCAP;
        for (unsigned e = wid; e < n; e += 16) {
            unsigned ent = queue[e];
            int r = ent >> 10;
            int v = ent & 1023;
            const float4 xa = *(const float4*)(Af + r * AF_STRIDE + lane * 4);
            const float4 ca = *(const float4*)(cb + (size_t)v * DQ + lane * 4);
            float s = xa.x * ca.x + xa.y * ca.y + xa.z * ca.z + xa.w * ca.w;
#pragma unroll
            for (int off = 16; off; off >>= 1)
                s += __shfl_down_sync(0xffffffffu, s, off);
            if (lane == 0) {
                float score = fmaf(-2.f, s, csq_s[v]);
                unsigned long long pk =
                    ((unsigned long long)fford(score) << 32) | (unsigned)v;
                atomicMin(&res[r], pk);
            }
        }
    }
    __syncthreads();

    // Write codes (as float) and fused quantized gather
    if (tid < TILE_M)
        codes[(size_t)b * TQ + t0 + tid] = (float)(unsigned)(res[tid] & 1023u);

    {
        int t = tid & 127;
        int dh = tid >> 7;                 // 0..3: d-quarters
        int v = (int)(res[t] & 1023u);
        const float* crow = cb + (size_t)v * DQ + dh * 32;
        float* q = quant + (size_t)b * DQ * TQ + (size_t)(dh * 32) * TQ + t0 + t;
#pragma unroll
        for (int i = 0; i < 8; i++) {
            float4 c4 = *(const float4*)(crow + i * 4);
            q[(i * 4 + 0) * TQ] = c4.x;
            q[(i * 4 + 1) * TQ] = c4.y;
            q[(i * 4 + 2) * TQ] = c4.z;
            q[(i * 4 + 3) * TQ] = c4.w;
        }
    }
}

// ---------------------------------------------------------------------------
extern "C" void kernel_launch(void* const* d_in, const int* in_sizes, int n_in,
                              void* d_out, int out_size) {
    const float* latents = (const float*)d_in[0];   // (B, D, T) fp32
    const float* codebook = (const float*)d_in[1];  // (V, D)    fp32

    float* codes = (float*)d_out;             // B*T floats
    float* quant = (float*)d_out + BQ * TQ;   // B*D*T floats

    cudaFuncSetAttribute(vq_kernel,
                         cudaFuncAttributeMaxDynamicSharedMemorySize,
                         SMEM_TOTAL);

    prep1_kernel<<<(VQ * 32) / 256, 256>>>(codebook);
    prep2_kernel<<<1, 1024>>>(codebook);

    dim3 grid(TQ / TILE_M, BQ);   // (32, 16) = 512 blocks
    vq_kernel<<<grid, NTHREADS, SMEM_TOTAL>>>(latents, codebook, codes, quant);
}

// round 11
// speedup vs baseline: 1.8060x; 1.8060x over previous
#include <cuda_runtime.h>
#include <cuda_bf16.h>
#include <cstdint>

// Problem constants
#define BQ 16
#define DQ 128
#define TQ 4096
#define VQ 1024

#define TILE_M 128
#define TILE_N 128
#define NCHUNK 8
#define MARGIN 3.0f
#define QCAP 4096
#define NTHREADS 512

// Dynamic SMEM layout (bytes)
#define OFF_RES    0          // 128 x u64 packed (score,idx)
#define OFF_ROWMIN 1024       // 128 x u32 (order-uint running cheap min)
#define OFF_QN     1536       // queue counter
#define OFF_CSQ    2048       // 1024 floats
#define OFF_QUEUE  6144       // QCAP x u32 (16KB)
#define OFF_AF     22528      // fp32 A [128][AF_STRIDE]
#define AF_STRIDE  132
#define OFF_AH     90112      // bf16 A tile 32KB (swizzled)
#define OFF_B      122880     // bf16 B tiles, 3 x 32KB (triple buffer)
#define BTILE      32768
#define SMEM_TOTAL 221184

__device__ float g_csq[VQ];
__device__ __nv_bfloat16 g_ch[VQ * DQ];

// ---------------------------------------------------------------------------
__device__ __forceinline__ uint32_t smem_u32(const void* p) {
    uint32_t a;
    asm("{ .reg .u64 t; cvta.to.shared.u64 t, %1; cvt.u32.u64 %0, t; }"
        : "=r"(a) : "l"(p));
    return a;
}

#define LDMX4(r, addr) \
    asm volatile("ldmatrix.sync.aligned.m8n8.x4.shared.b16 {%0,%1,%2,%3}, [%4];" \
        : "=r"((r)[0]), "=r"((r)[1]), "=r"((r)[2]), "=r"((r)[3]) \
        : "r"(addr))

__device__ __forceinline__ void mma_bf16(float* c, const uint32_t* a,
                                         const uint32_t* b) {
    asm volatile(
        "mma.sync.aligned.m16n8k16.row.col.f32.bf16.bf16.f32 "
        "{%0,%1,%2,%3}, {%4,%5,%6,%7}, {%8,%9}, {%0,%1,%2,%3};"
        : "+f"(c[0]), "+f"(c[1]), "+f"(c[2]), "+f"(c[3])
        : "r"(a[0]), "r"(a[1]), "r"(a[2]), "r"(a[3]), "r"(b[0]), "r"(b[1]));
}

#define CP_ASYNC16(dst, src) \
    asm volatile("cp.async.cg.shared.global [%0], [%1], 16;" \
        :: "r"(dst), "l"(src))
#define CP_COMMIT() asm volatile("cp.async.commit_group;" ::: "memory")
#define CP_WAIT2() asm volatile("cp.async.wait_group 2;" ::: "memory")

// Swizzled byte offset inside a (rows x 128) bf16 tile (256B rows, 16B chunks,
// chunk column XOR'd with row%8 -> conflict-free ldmatrix).
__device__ __forceinline__ uint32_t tswz(int row, int col2b) {
    return (uint32_t)(row * 256 + ((((col2b >> 3) ^ (row & 7)) << 4) |
                                   ((col2b & 7) * 2)));
}

// Order-preserving float <-> uint
__device__ __forceinline__ unsigned fford(float f) {
    unsigned u = __float_as_uint(f);
    return (u & 0x80000000u) ? ~u : (u | 0x80000000u);
}
__device__ __forceinline__ float fford_inv(unsigned u) {
    unsigned b = (u & 0x80000000u) ? (u & 0x7fffffffu) : ~u;
    return __uint_as_float(b);
}

// ---------------------------------------------------------------------------
// Prep: per code row v, csq[v] and bf16-hi conversion. One warp per row.
// ---------------------------------------------------------------------------
__global__ void prep_kernel(const float* __restrict__ cb) {
    int v = (blockIdx.x * blockDim.x + threadIdx.x) >> 5;
    int lane = threadIdx.x & 31;
    if (v >= VQ) return;
    const float4 x4 = *(const float4*)(cb + (size_t)v * DQ + lane * 4);
    float s = x4.x * x4.x + x4.y * x4.y + x4.z * x4.z + x4.w * x4.w;
#pragma unroll
    for (int off = 16; off; off >>= 1)
        s += __shfl_down_sync(0xffffffffu, s, off);
    if (lane == 0) g_csq[v] = s;
    __nv_bfloat162 p0 = __nv_bfloat162(__float2bfloat16(x4.x),
                                       __float2bfloat16(x4.y));
    __nv_bfloat162 p1 = __nv_bfloat162(__float2bfloat16(x4.z),
                                       __float2bfloat16(x4.w));
    *(__nv_bfloat162*)(g_ch + (size_t)v * DQ + lane * 4) = p0;
    *(__nv_bfloat162*)(g_ch + (size_t)v * DQ + lane * 4 + 2) = p1;
}

// ---------------------------------------------------------------------------
// Main: cheap bf16 GEMM screen -> warp-aggregated candidate queue -> exact
// fp32 rescore -> codes + fused quantized gather.  512 threads, 16 warps
// (4x4), warp tile 32x32, CTA tile 128x128x128, triple-buffered B, one
// syncthreads per chunk, ballot-aggregated queue inserts.
// ---------------------------------------------------------------------------
__global__ void __launch_bounds__(NTHREADS, 1)
vq_kernel(const float* __restrict__ latents, const float* __restrict__ cb,
          float* __restrict__ codes, float* __restrict__ quant) {
    extern __shared__ unsigned char sm[];
    const uint32_t smb = smem_u32(sm);
    const int tid = threadIdx.x;
    const int lane = tid & 31;
    const int wid = tid >> 5;
    const int warp_m = wid & 3;    // 4 m-tiles of 32 rows
    const int warp_n = wid >> 2;   // 4 n-tiles of 32 cols
    const int b = blockIdx.y;
    const int t0 = blockIdx.x * TILE_M;

    unsigned long long* res = (unsigned long long*)(sm + OFF_RES);
    unsigned* rowmin = (unsigned*)(sm + OFF_ROWMIN);
    unsigned* qn = (unsigned*)(sm + OFF_QN);
    float* csq_s = (float*)(sm + OFF_CSQ);
    float* Af = (float*)(sm + OFF_AF);
    unsigned* queue = (unsigned*)(sm + OFF_QUEUE);

    // Prefetch B chunks 0 and 1 (two committed groups)
#pragma unroll
    for (int pc = 0; pc < 2; pc++) {
        const __nv_bfloat16* src = g_ch + (size_t)pc * TILE_N * DQ;
        uint32_t dbase = smb + OFF_B + pc * BTILE;
        for (int i = tid; i < 2048; i += NTHREADS) {
            int n = i >> 4, c = i & 15;
            CP_ASYNC16(dbase + tswz(n, c * 8),
                       (const void*)(src + n * DQ + c * 8));
        }
        CP_COMMIT();
    }

    if (tid < TILE_M) {
        res[tid] = ~0ull;
        rowmin[tid] = 0xFFFFFFFFu;
    }
    if (tid == 0) *qn = 0;
    for (int i = tid; i < VQ; i += NTHREADS) csq_s[i] = g_csq[i];

    // A: latents[b][d][t0+t] -> bf16-hi swizzled tile + fp32 copy
    {
        const float* xg = latents + (size_t)b * DQ * TQ + t0;
        for (int idx = tid; idx < DQ * TILE_M; idx += NTHREADS) {
            int d = idx >> 7;
            int t = idx & 127;     // coalesced over t
            float x = xg[(size_t)d * TQ + t];
            *(__nv_bfloat16*)(sm + OFF_AH + tswz(t, d)) = __float2bfloat16(x);
            Af[t * AF_STRIDE + d] = x;
        }
    }

    // Per-thread ldmatrix constants (layout validated in R5-R9)
    const int arow_in16 = lane & 15;
    const int kca = lane >> 4;
    const int brow_in16 = (lane & 7) | ((lane >> 4) << 3);
    const int kcb = (lane >> 3) & 1;

    int axr[2];
    uint32_t abase[2];
#pragma unroll
    for (int mi = 0; mi < 2; mi++) {
        int row = warp_m * 32 + mi * 16 + arow_in16;
        axr[mi] = row & 7;
        abase[mi] = (uint32_t)(row * 256);
    }
    int bxr[2];
    uint32_t bbase[2];
#pragma unroll
    for (int n4 = 0; n4 < 2; n4++) {
        int row = warp_n * 32 + n4 * 16 + brow_in16;
        bxr[n4] = row & 7;
        bbase[n4] = (uint32_t)(row * 256);
    }

    for (int vc = 0; vc < NCHUNK; vc++) {
        const int v0 = vc * TILE_N;

        // Prefetch chunk vc+2 into buffer (vc+2)%3; commit keeps group count
        // invariant for CP_WAIT2 even when the body is empty.
        if (vc + 2 < NCHUNK) {
            const __nv_bfloat16* src = g_ch + (size_t)(v0 + 2 * TILE_N) * DQ;
            uint32_t dbase = smb + OFF_B + ((vc + 2) % 3) * BTILE;
            for (int i = tid; i < 2048; i += NTHREADS) {
                int n = i >> 4, c = i & 15;
                CP_ASYNC16(dbase + tswz(n, c * 8),
                           (const void*)(src + n * DQ + c * 8));
            }
        }
        CP_COMMIT();
        CP_WAIT2();        // chunk vc's group complete
        __syncthreads();   // B[vc] visible; all warps past B[vc-3] reads

        float acc[2][4][4];
#pragma unroll
        for (int mi = 0; mi < 2; mi++)
#pragma unroll
            for (int ni = 0; ni < 4; ni++)
#pragma unroll
                for (int q = 0; q < 4; q++) acc[mi][ni][q] = 0.f;

        const uint32_t bsm = smb + OFF_B + (vc % 3) * BTILE;
#pragma unroll
        for (int ks = 0; ks < 8; ks++) {
            uint32_t aH[2][4];
#pragma unroll
            for (int mi = 0; mi < 2; mi++) {
                uint32_t co = (uint32_t)((((ks << 1) | kca) ^ axr[mi]) << 4);
                LDMX4(aH[mi], smb + OFF_AH + abase[mi] + co);
            }
            uint32_t bH[4][2];
#pragma unroll
            for (int n4 = 0; n4 < 2; n4++) {
                uint32_t co = (uint32_t)((((ks << 1) | kcb) ^ bxr[n4]) << 4);
                uint32_t r[4];
                LDMX4(r, bsm + bbase[n4] + co);
                bH[n4 * 2][0] = r[0]; bH[n4 * 2][1] = r[1];
                bH[n4 * 2 + 1][0] = r[2]; bH[n4 * 2 + 1][1] = r[3];
            }
#pragma unroll
            for (int mi = 0; mi < 2; mi++)
#pragma unroll
                for (int ni = 0; ni < 4; ni++)
                    mma_bf16(acc[mi][ni], aH[mi], bH[ni]);
        }

        // Convert acc -> cheap scores in place, track per-thread row mins
        float rm[4];
#pragma unroll
        for (int j = 0; j < 4; j++) rm[j] = 3.4e38f;
#pragma unroll
        for (int ni = 0; ni < 4; ni++) {
            int col0 = v0 + warp_n * 32 + ni * 8 + (lane & 3) * 2;
            float cs0 = csq_s[col0], cs1 = csq_s[col0 + 1];
#pragma unroll
            for (int mi = 0; mi < 2; mi++) {
                float* c = acc[mi][ni];
                c[0] = fmaf(-2.f, c[0], cs0);
                c[1] = fmaf(-2.f, c[1], cs1);
                c[2] = fmaf(-2.f, c[2], cs0);
                c[3] = fmaf(-2.f, c[3], cs1);
                float m01 = fminf(c[0], c[1]), m23 = fminf(c[2], c[3]);
                if (m01 < rm[mi * 2]) rm[mi * 2] = m01;
                if (m23 < rm[mi * 2 + 1]) rm[mi * 2 + 1] = m23;
            }
        }
        // rowmin monotone-decreasing: no barrier needed (stale read = safe
        // looser threshold; writer of true min reads its own update).
#pragma unroll
        for (int j = 0; j < 4; j++) {
            int row = warp_m * 32 + (j >> 1) * 16 + (j & 1) * 8 + (lane >> 2);
            atomicMin(&rowmin[row], fford(rm[j]));
        }

        // Warp-aggregated candidate insertion (ballot + single atomicAdd)
#pragma unroll
        for (int mi = 0; mi < 2; mi++) {
            int rA = warp_m * 32 + mi * 16 + (lane >> 2);
            float thA = fford_inv(rowmin[rA]) + MARGIN;
            float thB = fford_inv(rowmin[rA + 8]) + MARGIN;
#pragma unroll
            for (int ni = 0; ni < 4; ni++) {
                int col0 = v0 + warp_n * 32 + ni * 8 + (lane & 3) * 2;
                const float* c = acc[mi][ni];
                bool c0 = c[0] <= thA;
                bool c1 = c[1] <= thA;
                bool c2 = c[2] <= thB;
                bool c3 = c[3] <= thB;
                unsigned m0 = __ballot_sync(0xffffffffu, c0);
                unsigned m1 = __ballot_sync(0xffffffffu, c1);
                unsigned m2 = __ballot_sync(0xffffffffu, c2);
                unsigned m3 = __ballot_sync(0xffffffffu, c3);
                unsigned p0 = __popc(m0), p1 = __popc(m1);
                unsigned p2 = __popc(m2), p3 = __popc(m3);
                unsigned tot = p0 + p1 + p2 + p3;
                if (tot) {   // warp-uniform branch
                    unsigned base = 0;
                    if (lane == 0) base = atomicAdd(qn, tot);
                    base = __shfl_sync(0xffffffffu, base, 0);
                    unsigned lt = (1u << lane) - 1u;
                    unsigned o0 = base + __popc(m0 & lt);
                    unsigned o1 = base + p0 + __popc(m1 & lt);
                    unsigned o2 = base + p0 + p1 + __popc(m2 & lt);
                    unsigned o3 = base + p0 + p1 + p2 + __popc(m3 & lt);
                    if (c0 && o0 < QCAP)
                        queue[o0] = ((unsigned)rA << 10) | col0;
                    if (c1 && o1 < QCAP)
                        queue[o1] = ((unsigned)rA << 10) | (col0 + 1);
                    if (c2 && o2 < QCAP)
                        queue[o2] = ((unsigned)(rA + 8) << 10) | col0;
                    if (c3 && o3 < QCAP)
                        queue[o3] = ((unsigned)(rA + 8) << 10) | (col0 + 1);
                }
            }
        }
    }
    __syncthreads();

    // Exact fp32 rescore of candidates: one warp per queue entry
    {
        unsigned n = *qn;
        if (n > QCAP) n = QCAP;
        for (unsigned e = wid; e < n; e += 16) {
            unsigned ent = queue[e];
            int r = ent >> 10;
            int v = ent & 1023;
            const float4 xa = *(const float4*)(Af + r * AF_STRIDE + lane * 4);
            const float4 ca = *(const float4*)(cb + (size_t)v * DQ + lane * 4);
            float s = xa.x * ca.x + xa.y * ca.y + xa.z * ca.z + xa.w * ca.w;
#pragma unroll
            for (int off = 16; off; off >>= 1)
                s += __shfl_down_sync(0xffffffffu, s, off);
            if (lane == 0) {
                float score = fmaf(-2.f, s, csq_s[v]);
                unsigned long long pk =
                    ((unsigned long long)fford(score) << 32) | (unsigned)v;
                atomicMin(&res[r], pk);
            }
        }
    }
    __syncthreads();

    // Write codes (as float) and fused quantized gather
    if (tid < TILE_M)
        codes[(size_t)b * TQ + t0 + tid] = (float)(unsigned)(res[tid] & 1023u);

    {
        int t = tid & 127;
        int dh = tid >> 7;                 // 0..3: d-quarters
        int v = (int)(res[t] & 1023u);
        const float* crow = cb + (size_t)v * DQ + dh * 32;
        float* q = quant + (size_t)b * DQ * TQ + (size_t)(dh * 32) * TQ + t0 + t;
#pragma unroll
        for (int i = 0; i < 8; i++) {
            float4 c4 = *(const float4*)(crow + i * 4);
            q[(i * 4 + 0) * TQ] = c4.x;
            q[(i * 4 + 1) * TQ] = c4.y;
            q[(i * 4 + 2) * TQ] = c4.z;
            q[(i * 4 + 3) * TQ] = c4.w;
        }
    }
}

// ---------------------------------------------------------------------------
extern "C" void kernel_launch(void* const* d_in, const int* in_sizes, int n_in,
                              void* d_out, int out_size) {
    const float* latents = (const float*)d_in[0];   // (B, D, T) fp32
    const float* codebook = (const float*)d_in[1];  // (V, D)    fp32

    float* codes = (float*)d_out;             // B*T floats
    float* quant = (float*)d_out + BQ * TQ;   // B*D*T floats

    cudaFuncSetAttribute(vq_kernel,
                         cudaFuncAttributeMaxDynamicSharedMemorySize,
                         SMEM_TOTAL);

    prep_kernel<<<(VQ * 32) / 256, 256>>>(codebook);

    dim3 grid(TQ / TILE_M, BQ);   // (32, 16) = 512 blocks
    vq_kernel<<<grid, NTHREADS, SMEM_TOTAL>>>(latents, codebook, codes, quant);
}